// round 1
// baseline (speedup 1.0000x reference)
#include <cuda_runtime.h>

// out[i, :] = values[i] * W_D[layer_idx[i], feat_idx[i], :]
// W_D: (12, 16384, 768) fp32; nnz = 131072; d_model = 768.
// One CTA per row; 192 threads; one float4 (16B) per thread -> 3072B row.

#define D_SAE   16384
#define D_MODEL 768
#define VEC_PER_ROW (D_MODEL / 4)   // 192

__global__ __launch_bounds__(VEC_PER_ROW)
void gather_scale_kernel(const float4* __restrict__ W,      // W_D as float4
                         const float*  __restrict__ vals,   // values (nnz)
                         const int*    __restrict__ li,     // layer_idx (nnz)
                         const int*    __restrict__ fi,     // feat_idx  (nnz)
                         float4*       __restrict__ out)    // (nnz, 768) as float4
{
    const int row = blockIdx.x;
    const int c   = threadIdx.x;

    // scalar row metadata — broadcast via L1
    const int   layer = __ldg(&li[row]);
    const int   feat  = __ldg(&fi[row]);
    const float v     = __ldg(&vals[row]);

    // (layer * D_SAE + feat) rows of 192 float4 each; max index 37.7M < 2^31
    const unsigned int src = (unsigned int)(layer * D_SAE + feat) * VEC_PER_ROW + c;

    float4 d = __ldg(&W[src]);
    d.x *= v; d.y *= v; d.z *= v; d.w *= v;

    out[(unsigned int)row * VEC_PER_ROW + c] = d;
}

extern "C" void kernel_launch(void* const* d_in, const int* in_sizes, int n_in,
                              void* d_out, int out_size)
{
    // metadata order: W_D, values, layer_idx, pos_idx, feat_idx
    const float4* W    = (const float4*)d_in[0];
    const float*  vals = (const float*) d_in[1];
    const int*    li   = (const int*)   d_in[2];
    // d_in[3] = pos_idx (unused)
    const int*    fi   = (const int*)   d_in[4];
    float4*       out  = (float4*)      d_out;

    const int nnz = in_sizes[1];  // 131072

    gather_scale_kernel<<<nnz, VEC_PER_ROW>>>(W, vals, li, fi, out);
}

// round 3
// speedup vs baseline: 1.2800x; 1.2800x over previous
#include <cuda_runtime.h>

// out[i, :] = values[i] * W_D[layer_idx[i], feat_idx[i], :]
// W_D: (12, 16384, 768) fp32; nnz = 131072; d_model = 768 (3072 B/row).
// 4 rows per CTA, 192 threads; each thread does 4 independent float4 gathers
// (MLP=4) and 4 streaming stores (__stcs keeps L2 for the W gather).

#define D_SAE   16384
#define D_MODEL 768
#define VEC_PER_ROW (D_MODEL / 4)   // 192
#define ROWS_PER_CTA 4

__global__ __launch_bounds__(VEC_PER_ROW)
void gather_scale_kernel(const float4* __restrict__ W,
                         const float*  __restrict__ vals,
                         const int*    __restrict__ li,
                         const int*    __restrict__ fi,
                         float4*       __restrict__ out)
{
    const int row0 = blockIdx.x * ROWS_PER_CTA;
    const int c    = threadIdx.x;

    unsigned int src[ROWS_PER_CTA];
    float        v[ROWS_PER_CTA];

#pragma unroll
    for (int r = 0; r < ROWS_PER_CTA; r++) {
        const int row   = row0 + r;
        const int layer = __ldg(&li[row]);
        const int feat  = __ldg(&fi[row]);
        v[r]            = __ldg(&vals[row]);
        src[r] = (unsigned int)(layer * D_SAE + feat) * VEC_PER_ROW + c;
    }

    // Issue all 4 gathers back-to-back (independent -> 4 outstanding loads/thread)
    float4 d[ROWS_PER_CTA];
#pragma unroll
    for (int r = 0; r < ROWS_PER_CTA; r++)
        d[r] = __ldg(&W[src[r]]);

#pragma unroll
    for (int r = 0; r < ROWS_PER_CTA; r++) {
        float4 o = d[r];
        o.x *= v[r]; o.y *= v[r]; o.z *= v[r]; o.w *= v[r];
        // streaming store: evict-first, don't pollute L2 (W reuse lives there)
        __stcs(&out[(unsigned int)(row0 + r) * VEC_PER_ROW + c], o);
    }
}

extern "C" void kernel_launch(void* const* d_in, const int* in_sizes, int n_in,
                              void* d_out, int out_size)
{
    const float4* W    = (const float4*)d_in[0];
    const float*  vals = (const float*) d_in[1];
    const int*    li   = (const int*)   d_in[2];
    // d_in[3] = pos_idx (unused)
    const int*    fi   = (const int*)   d_in[4];
    float4*       out  = (float4*)      d_out;

    const int nnz = in_sizes[1];                 // 131072 (divisible by 4)
    const int grid = nnz / ROWS_PER_CTA;         // 32768

    gather_scale_kernel<<<grid, VEC_PER_ROW>>>(W, vals, li, fi, out);
}